// round 6
// baseline (speedup 1.0000x reference)
#include <cuda_runtime.h>
#include <math.h>

// Problem dims (fixed by dataset): B=1024, I=512, O=512.
#define I_DIM 512
#define O_DIM 512

#define BM 64
#define BN 64
#define BK 16          // k per tile; 32 tiles
#define K2 (BK / 2)    // k-pair steps per tile

// Scratch (allocation-free: __device__ globals)
__device__ __align__(16) float g_s2 [O_DIM * I_DIM];   // inv^2 + 1e-32
__device__ __align__(16) float g_nc2[O_DIM * I_DIM];   // -2 * c * s2
__device__ __align__(16) float g_K  [O_DIM];           // sum_i c^2 * s2

typedef unsigned long long u64;

// d = a*b + d   (packed f32x2, sm_100+, PTX-only)
__device__ __forceinline__ void ffma2_acc(u64 &d, u64 a, u64 b) {
    asm("fma.rn.f32x2 %0, %1, %2, %0;" : "+l"(d) : "l"(a), "l"(b));
}
// d = a*b + c
__device__ __forceinline__ u64 ffma2(u64 a, u64 b, u64 c) {
    u64 d;
    asm("fma.rn.f32x2 %0, %1, %2, %3;" : "=l"(d) : "l"(a), "l"(b), "l"(c));
    return d;
}

// ---------------------------------------------------------------------------
// Prep: s2 = v^2 + eps, nc2 = -2*c*s2, K[o] = sum c^2 s2.
// ---------------------------------------------------------------------------
__global__ void fgn_prep_kernel(const float* __restrict__ centers,
                                const float* __restrict__ inv_covars)
{
    int o = blockIdx.x;
    int t = threadIdx.x;
    __shared__ float red[256];

    float ksum = 0.0f;
    for (int i = t; i < I_DIM; i += 256) {
        float v  = inv_covars[o * I_DIM + i];
        float c  = centers   [o * I_DIM + i];
        float s2 = v * v + 1e-32f;
        float cs = c * s2;
        g_s2 [o * I_DIM + i] = s2;
        g_nc2[o * I_DIM + i] = -2.0f * cs;
        ksum += c * cs;
    }
    red[t] = ksum;
    __syncthreads();
    #pragma unroll
    for (int s = 128; s > 0; s >>= 1) {
        if (t < s) red[t] += red[t + s];
        __syncthreads();
    }
    if (t == 0) g_K[o] = red[0];
}

// ---------------------------------------------------------------------------
// Fused layer via k-packed f32x2 FMAs + operand-eliminated Mahalanobis:
//   L[b,o] = x.w ;  g[b,o] = sum_k x*(s2*x + nc2)   (nc2 = -2 c s2)
//   out    = (L + bias) * exp(-(g + K))
//
// 256 threads = 32 tx (n) x 8 ty (m); thread tile 8m x 2n.
// Smem: k-pair-major float2 tiles  Xp/Wp/Sp/Cp [K2][dim]  (16 KB total).
// Per thread per 2k: 7 LDS.128 + 48 FFMA2 (96 FMAs)  -> FFMA2/smem balanced.
// ---------------------------------------------------------------------------
__global__ __launch_bounds__(256, 1)
void fgn_main_kernel(const float* __restrict__ X,
                     const float* __restrict__ W,
                     const float* __restrict__ bias,
                     float* __restrict__ out)
{
    // float2 pair tiles, viewed as float arrays: [k2][2*rows]
    __shared__ float Xp[K2][2 * BM];   // 4 KB
    __shared__ float Wp[K2][2 * BN];   // 4 KB
    __shared__ float Sp[K2][2 * BN];   // 4 KB
    __shared__ float Cp[K2][2 * BN];   // 4 KB

    const int tid = threadIdx.x;
    const int tx  = tid & 31;          // n lane: n = 2*tx + {0,1}
    const int ty  = tid >> 5;          // m lane: m = 8*ty + {0..7}
    const int m0  = blockIdx.y * BM;
    const int n0  = blockIdx.x * BN;

    // Staging map: 64 rows x 4 float4 of k per tile; 1 float4 per thread/matrix.
    const int row = tid & 63;
    const int q4  = tid >> 6;          // 0..3 (float4 index within row's BK)

    const float4* gX = (const float4*)&X    [(size_t)(m0 + row) * I_DIM] + q4;
    const float4* gW = (const float4*)&W    [(size_t)(n0 + row) * I_DIM] + q4;
    const float4* gS = (const float4*)&g_s2 [(size_t)(n0 + row) * I_DIM] + q4;
    const float4* gC = (const float4*)&g_nc2[(size_t)(n0 + row) * I_DIM] + q4;

    u64 accL[8][2] = {};   // [mi][j], each u64 = 2 k-partials
    u64 accG[8][2] = {};

    // transpose float4 -> two k-pair float2 rows; STS.64, conflict-free
    auto sts_all = [&](float4 xv, float4 wv, float4 sv, float4 cv) {
        *(float2*)&Xp[2 * q4    ][2 * row] = make_float2(xv.x, xv.y);
        *(float2*)&Xp[2 * q4 + 1][2 * row] = make_float2(xv.z, xv.w);
        *(float2*)&Wp[2 * q4    ][2 * row] = make_float2(wv.x, wv.y);
        *(float2*)&Wp[2 * q4 + 1][2 * row] = make_float2(wv.z, wv.w);
        *(float2*)&Sp[2 * q4    ][2 * row] = make_float2(sv.x, sv.y);
        *(float2*)&Sp[2 * q4 + 1][2 * row] = make_float2(sv.z, sv.w);
        *(float2*)&Cp[2 * q4    ][2 * row] = make_float2(cv.x, cv.y);
        *(float2*)&Cp[2 * q4 + 1][2 * row] = make_float2(cv.z, cv.w);
    };

    auto compute = [&]() {
        #pragma unroll
        for (int k2 = 0; k2 < K2; k2++) {
            // x: 8 m-pairs, contiguous 64B -> 4 LDS.128
            ulonglong2 xa = *(const ulonglong2*)&Xp[k2][16 * ty];
            ulonglong2 xb = *(const ulonglong2*)&Xp[k2][16 * ty + 4];
            ulonglong2 xc = *(const ulonglong2*)&Xp[k2][16 * ty + 8];
            ulonglong2 xd = *(const ulonglong2*)&Xp[k2][16 * ty + 12];
            u64 xm[8] = {xa.x, xa.y, xb.x, xb.y, xc.x, xc.y, xd.x, xd.y};
            // w/s2/nc2: 2 n-pairs each, 16B -> 1 LDS.128 each
            ulonglong2 wv = *(const ulonglong2*)&Wp[k2][4 * tx];
            ulonglong2 sv = *(const ulonglong2*)&Sp[k2][4 * tx];
            ulonglong2 cv = *(const ulonglong2*)&Cp[k2][4 * tx];
            u64 wp[2] = {wv.x, wv.y};
            u64 sp[2] = {sv.x, sv.y};
            u64 cp[2] = {cv.x, cv.y};

            #pragma unroll
            for (int mi = 0; mi < 8; mi++) {
                #pragma unroll
                for (int j = 0; j < 2; j++) {
                    u64 t = ffma2(sp[j], xm[mi], cp[j]);   // s2*x - 2cs2
                    ffma2_acc(accG[mi][j], xm[mi], t);     // g += x*t
                    ffma2_acc(accL[mi][j], xm[mi], wp[j]); // L += x*w
                }
            }
        }
    };

    // Prologue: stage tile 0
    sts_all(gX[0], gW[0], gS[0], gC[0]);
    __syncthreads();

    // Main loop: register-prefetch next tile, compute current, swap
    #pragma unroll 1
    for (int it = 1; it < I_DIM / BK; it++) {
        float4 nx = gX[it * (BK / 4)];
        float4 nw = gW[it * (BK / 4)];
        float4 ns = gS[it * (BK / 4)];
        float4 nc = gC[it * (BK / 4)];
        compute();
        __syncthreads();
        sts_all(nx, nw, ns, nc);
        __syncthreads();
    }
    compute();

    // Epilogue: fold k-pair partials; out = (L+bias)*exp(-(G+K))
    const float2 bv = *(const float2*)&bias[n0 + 2 * tx];
    const float2 kv = *(const float2*)&g_K [n0 + 2 * tx];
    const float bb[2] = {bv.x, bv.y};
    const float kk[2] = {kv.x, kv.y};

    #pragma unroll
    for (int mi = 0; mi < 8; mi++) {
        int m = m0 + 8 * ty + mi;
        float o2[2];
        #pragma unroll
        for (int j = 0; j < 2; j++) {
            float L = __uint_as_float((unsigned)(accL[mi][j] & 0xffffffffu))
                    + __uint_as_float((unsigned)(accL[mi][j] >> 32));
            float G = __uint_as_float((unsigned)(accG[mi][j] & 0xffffffffu))
                    + __uint_as_float((unsigned)(accG[mi][j] >> 32));
            o2[j] = (L + bb[j]) * expf(-(G + kk[j]));
        }
        *(float2*)&out[(size_t)m * O_DIM + n0 + 2 * tx] = make_float2(o2[0], o2[1]);
    }
}

// ---------------------------------------------------------------------------
// Launch. Inputs: inputs[B,I], weights[O,I], biases[O], centers[O,I],
// inv_covars[O,I]. Output: [B,O] fp32.
// ---------------------------------------------------------------------------
extern "C" void kernel_launch(void* const* d_in, const int* in_sizes, int n_in,
                              void* d_out, int out_size)
{
    const float* X    = (const float*)d_in[0];
    const float* W    = (const float*)d_in[1];
    const float* bias = (const float*)d_in[2];
    const float* C    = (const float*)d_in[3];
    const float* V    = (const float*)d_in[4];

    const int O = in_sizes[2];               // 512
    const int I = in_sizes[1] / O;           // 512
    const int B = in_sizes[0] / I;           // 1024
    (void)n_in; (void)out_size;

    fgn_prep_kernel<<<O, 256>>>(C, V);

    dim3 grid(O / BN, B / BM);               // 8 x 16 = 128 CTAs
    fgn_main_kernel<<<grid, 256>>>(X, W, bias, (float*)d_out);
}

// round 7
// speedup vs baseline: 1.8175x; 1.8175x over previous
#include <cuda_runtime.h>
#include <math.h>

// Problem dims (fixed by dataset): B=1024, I=512, O=512.
#define I_DIM 512
#define O_DIM 512

#define BM 64
#define BN 64
#define BK 32
#define PAD 33   // stride pad: conflict-free scalar LDS/STS

// Scratch (allocation-free: __device__ globals)
__device__ __align__(16) float g_s2 [O_DIM * I_DIM];   // inv^2 + 1e-32
__device__ __align__(16) float g_nc2[O_DIM * I_DIM];   // -2 * c * s2
__device__ __align__(16) float g_K  [O_DIM];           // sum_i c^2 * s2

// ---------------------------------------------------------------------------
// Prep: s2 = v^2 + eps, nc2 = -2*c*s2, K[o] = sum c^2 s2.
// ---------------------------------------------------------------------------
__global__ void fgn_prep_kernel(const float* __restrict__ centers,
                                const float* __restrict__ inv_covars)
{
    int o = blockIdx.x;
    int t = threadIdx.x;
    __shared__ float red[256];

    float ksum = 0.0f;
    for (int i = t; i < I_DIM; i += 256) {
        float v  = inv_covars[o * I_DIM + i];
        float c  = centers   [o * I_DIM + i];
        float s2 = v * v + 1e-32f;
        float cs = c * s2;
        g_s2 [o * I_DIM + i] = s2;
        g_nc2[o * I_DIM + i] = -2.0f * cs;
        ksum += c * cs;
    }
    red[t] = ksum;
    __syncthreads();
    #pragma unroll
    for (int s = 128; s > 0; s >>= 1) {
        if (t < s) red[t] += red[t + s];
        __syncthreads();
    }
    if (t == 0) g_K[o] = red[0];
}

// ---------------------------------------------------------------------------
// Fused layer, scalar SIMT (R3 layout), high occupancy:
//   L[b,o] = x.w ;  g[b,o] = sum_k x*(s2*x + nc2)   (nc2 = -2 c s2)
//   out    = (L + bias) * exp(-(g + K))
//
// 512 threads = 32 tx (n) x 16 ty (m); thread tile 4m x 2n:
//   m = ty + 16*mi (stride-16) -> X loads broadcast (1 addr/warp)
//   n = tx + 32*ni (stride-32) -> W/S/C loads conflict-free (bank = tx)
// Per thread per k: 10 LDS.32 + 24 FFMA; 16 warps/SM (4/SMSP).
// ---------------------------------------------------------------------------
__global__ __launch_bounds__(512, 1)
void fgn_main_kernel(const float* __restrict__ X,
                     const float* __restrict__ W,
                     const float* __restrict__ bias,
                     float* __restrict__ out)
{
    __shared__ float Xs[BM][PAD];   // 8.25 KB
    __shared__ float Ws[BN][PAD];
    __shared__ float Ss[BN][PAD];
    __shared__ float Cs[BN][PAD];   // 33 KB total

    const int tid = threadIdx.x;
    const int tx  = tid & 31;          // n lane: n = tx + 32*ni
    const int ty  = tid >> 5;          // m lane: m = ty + 16*mi
    const int m0  = blockIdx.y * BM;
    const int n0  = blockIdx.x * BN;

    // Staging map: 64 rows x 32 k = 512 float4 per matrix; 1 per thread.
    const int row = tid & 63;
    const int q   = (tid >> 6) << 2;   // 0,4,...,28

    const float4* gX = (const float4*)&X    [(size_t)(m0 + row) * I_DIM + q];
    const float4* gW = (const float4*)&W    [(size_t)(n0 + row) * I_DIM + q];
    const float4* gS = (const float4*)&g_s2 [(size_t)(n0 + row) * I_DIM + q];
    const float4* gC = (const float4*)&g_nc2[(size_t)(n0 + row) * I_DIM + q];

    float accL[4][2] = {};
    float accG[4][2] = {};

    // Scalar transposed STS: within a warp rows span 32 values, q fixed
    // -> banks (row+q+j)&31 all distinct -> conflict-free.
    auto sts_all = [&](float4 xv, float4 wv, float4 sv, float4 cv) {
        Xs[row][q + 0] = xv.x; Xs[row][q + 1] = xv.y;
        Xs[row][q + 2] = xv.z; Xs[row][q + 3] = xv.w;
        Ws[row][q + 0] = wv.x; Ws[row][q + 1] = wv.y;
        Ws[row][q + 2] = wv.z; Ws[row][q + 3] = wv.w;
        Ss[row][q + 0] = sv.x; Ss[row][q + 1] = sv.y;
        Ss[row][q + 2] = sv.z; Ss[row][q + 3] = sv.w;
        Cs[row][q + 0] = cv.x; Cs[row][q + 1] = cv.y;
        Cs[row][q + 2] = cv.z; Cs[row][q + 3] = cv.w;
    };

    auto compute = [&]() {
        #pragma unroll 8
        for (int k = 0; k < BK; k++) {
            float xr[4], wr[2], sr[2], cr[2];
            #pragma unroll
            for (int mi = 0; mi < 4; mi++) xr[mi] = Xs[ty + 16 * mi][k];
            #pragma unroll
            for (int ni = 0; ni < 2; ni++) {
                wr[ni] = Ws[tx + 32 * ni][k];
                sr[ni] = Ss[tx + 32 * ni][k];
                cr[ni] = Cs[tx + 32 * ni][k];
            }
            #pragma unroll
            for (int mi = 0; mi < 4; mi++) {
                #pragma unroll
                for (int ni = 0; ni < 2; ni++) {
                    float t = fmaf(sr[ni], xr[mi], cr[ni]);   // s2*x - 2cs2
                    accG[mi][ni] = fmaf(xr[mi], t, accG[mi][ni]);
                    accL[mi][ni] = fmaf(xr[mi], wr[ni], accL[mi][ni]);
                }
            }
        }
    };

    // Prologue: stage tile 0
    sts_all(gX[0], gW[0], gS[0], gC[0]);
    __syncthreads();

    // Main loop: register-prefetch next tile, compute current, swap.
    #pragma unroll 1
    for (int it = 1; it < I_DIM / BK; it++) {
        float4 nx = gX[it * (BK / 4)];
        float4 nw = gW[it * (BK / 4)];
        float4 ns = gS[it * (BK / 4)];
        float4 nc = gC[it * (BK / 4)];
        compute();
        __syncthreads();
        sts_all(nx, nw, ns, nc);
        __syncthreads();
    }
    compute();

    // Epilogue: out = (L + bias) * exp(-(G + K)). Scalar STG.32, coalesced
    // across tx (stride-32 n tiling).
    float bb[2], kk[2];
    #pragma unroll
    for (int ni = 0; ni < 2; ni++) {
        bb[ni] = bias[n0 + tx + 32 * ni];
        kk[ni] = g_K [n0 + tx + 32 * ni];
    }
    #pragma unroll
    for (int mi = 0; mi < 4; mi++) {
        int m = m0 + ty + 16 * mi;
        #pragma unroll
        for (int ni = 0; ni < 2; ni++) {
            int n = n0 + tx + 32 * ni;
            float l = accL[mi][ni] + bb[ni];
            float g = accG[mi][ni] + kk[ni];
            out[(size_t)m * O_DIM + n] = l * expf(-g);
        }
    }
}

// ---------------------------------------------------------------------------
// Launch. Inputs: inputs[B,I], weights[O,I], biases[O], centers[O,I],
// inv_covars[O,I]. Output: [B,O] fp32.
// ---------------------------------------------------------------------------
extern "C" void kernel_launch(void* const* d_in, const int* in_sizes, int n_in,
                              void* d_out, int out_size)
{
    const float* X    = (const float*)d_in[0];
    const float* W    = (const float*)d_in[1];
    const float* bias = (const float*)d_in[2];
    const float* C    = (const float*)d_in[3];
    const float* V    = (const float*)d_in[4];

    const int O = in_sizes[2];               // 512
    const int I = in_sizes[1] / O;           // 512
    const int B = in_sizes[0] / I;           // 1024
    (void)n_in; (void)out_size;

    fgn_prep_kernel<<<O, 256>>>(C, V);

    dim3 grid(O / BN, B / BM);               // 8 x 16 = 128 CTAs
    fgn_main_kernel<<<grid, 512>>>(X, W, bias, (float*)d_out);
}

// round 9
// speedup vs baseline: 7.2944x; 4.0135x over previous
#include <cuda_runtime.h>
#include <cuda_bf16.h>
#include <cstdint>
#include <math.h>

// Problem dims (fixed by dataset): B=1024, I=512, O=512.
#define B_DIM 1024
#define I_DIM 512
#define O_DIM 512

#define TM 64
#define TN 64
#define KC 64                 // k per smem stage (128B bf16 rows -> SW128 swizzle)
#define NCH (I_DIM / KC)      // 8

typedef __nv_bfloat16 bf16;

// ---------------- device scratch (allocation-free) ----------------
__device__ __align__(16) bf16  g_xhi[B_DIM * I_DIM];
__device__ __align__(16) bf16  g_xlo[B_DIM * I_DIM];
__device__ __align__(16) bf16  g_x2 [B_DIM * I_DIM];
__device__ __align__(16) bf16  g_whi[O_DIM * I_DIM];
__device__ __align__(16) bf16  g_wlo[O_DIM * I_DIM];
__device__ __align__(16) bf16  g_s2 [O_DIM * I_DIM];   // v^2 + eps
__device__ __align__(16) bf16  g_nc2[O_DIM * I_DIM];   // -2 c (v^2+eps)
__device__ __align__(16) float g_K  [O_DIM];           // sum c^2 (v^2+eps), fp32

// ---------------- helpers ----------------
__device__ __forceinline__ unsigned pk2(float a, float b) {
    __nv_bfloat162 t;
    t.x = __float2bfloat16_rn(a);
    t.y = __float2bfloat16_rn(b);
    return *(unsigned*)&t;
}
__device__ __forceinline__ uint32_t smem_u32(const void* p) {
    uint32_t a;
    asm("{ .reg .u64 t; cvta.to.shared.u64 t, %1; cvt.u32.u64 %0, t; }" : "=r"(a) : "l"(p));
    return a;
}
__device__ __forceinline__ void cpa16(uint32_t dst, const void* src) {
    asm volatile("cp.async.cg.shared.global [%0], [%1], 16;" :: "r"(dst), "l"(src));
}
#define CP_COMMIT()  asm volatile("cp.async.commit_group;" ::: "memory")
#define CP_WAIT(n)   asm volatile("cp.async.wait_group %0;" :: "n"(n) : "memory")

#define LDMX4(r, addr)                                                        \
    asm volatile("ldmatrix.sync.aligned.m8n8.x4.shared.b16 {%0,%1,%2,%3}, [%4];" \
        : "=r"((r)[0]), "=r"((r)[1]), "=r"((r)[2]), "=r"((r)[3]) : "r"(addr))

__device__ __forceinline__ void mma16816(float* c, const uint32_t* a,
                                         uint32_t b0, uint32_t b1) {
    asm volatile(
        "mma.sync.aligned.m16n8k16.row.col.f32.bf16.bf16.f32 "
        "{%0,%1,%2,%3},{%4,%5,%6,%7},{%8,%9},{%0,%1,%2,%3};"
        : "+f"(c[0]), "+f"(c[1]), "+f"(c[2]), "+f"(c[3])
        : "r"(a[0]), "r"(a[1]), "r"(a[2]), "r"(a[3]), "r"(b0), "r"(b1));
}

// ---------------- prep kernels ----------------
__global__ void prep_x_kernel(const float* __restrict__ X) {
    int i = blockIdx.x * 256 + threadIdx.x;           // float4 index over B*I
    float4 x = ((const float4*)X)[i];
    float h0 = __bfloat162float(__float2bfloat16_rn(x.x));
    float h1 = __bfloat162float(__float2bfloat16_rn(x.y));
    float h2 = __bfloat162float(__float2bfloat16_rn(x.z));
    float h3 = __bfloat162float(__float2bfloat16_rn(x.w));
    ((uint2*)g_xhi)[i] = make_uint2(pk2(x.x, x.y), pk2(x.z, x.w));
    ((uint2*)g_xlo)[i] = make_uint2(pk2(x.x - h0, x.y - h1), pk2(x.z - h2, x.w - h3));
    ((uint2*)g_x2 )[i] = make_uint2(pk2(x.x * x.x, x.y * x.y), pk2(x.z * x.z, x.w * x.w));
}

__global__ void prep_w_kernel(const float* __restrict__ W) {
    int i = blockIdx.x * 256 + threadIdx.x;           // float4 index over O*I
    float4 w = ((const float4*)W)[i];
    float h0 = __bfloat162float(__float2bfloat16_rn(w.x));
    float h1 = __bfloat162float(__float2bfloat16_rn(w.y));
    float h2 = __bfloat162float(__float2bfloat16_rn(w.z));
    float h3 = __bfloat162float(__float2bfloat16_rn(w.w));
    ((uint2*)g_whi)[i] = make_uint2(pk2(w.x, w.y), pk2(w.z, w.w));
    ((uint2*)g_wlo)[i] = make_uint2(pk2(w.x - h0, w.y - h1), pk2(w.z - h2, w.w - h3));
}

__global__ void prep_cv_kernel(const float* __restrict__ C,
                               const float* __restrict__ V) {
    int o = blockIdx.x;
    int t = threadIdx.x;                              // 128 threads, 1 float4 each
    float4 c = ((const float4*)(C + (size_t)o * I_DIM))[t];
    float4 v = ((const float4*)(V + (size_t)o * I_DIM))[t];
    float s0 = v.x * v.x + 1e-32f, s1 = v.y * v.y + 1e-32f;
    float s2 = v.z * v.z + 1e-32f, s3 = v.w * v.w + 1e-32f;
    float ks = c.x * c.x * s0 + c.y * c.y * s1 + c.z * c.z * s2 + c.w * c.w * s3;
    ((uint2*)(g_s2  + (size_t)o * I_DIM))[t] =
        make_uint2(pk2(s0, s1), pk2(s2, s3));
    ((uint2*)(g_nc2 + (size_t)o * I_DIM))[t] =
        make_uint2(pk2(-2.0f * c.x * s0, -2.0f * c.y * s1),
                   pk2(-2.0f * c.z * s2, -2.0f * c.w * s3));
    __shared__ float red[4];
    #pragma unroll
    for (int d = 16; d > 0; d >>= 1) ks += __shfl_xor_sync(0xffffffffu, ks, d);
    if ((t & 31) == 0) red[t >> 5] = ks;
    __syncthreads();
    if (t == 0) g_K[o] = red[0] + red[1] + red[2] + red[3];
}

// ---------------- main mma.sync kernel ----------------
// Stage layout: 7 bf16 tiles of [64 rows][64 k] = 8 KB each, SW128-swizzled.
#define T_XHI 0
#define T_XLO 8192
#define T_X2  16384
#define T_WHI 24576
#define T_WLO 32768
#define T_S2  40960
#define T_NC2 49152
#define STAGE_BYTES 57344
#define SMEM_TOTAL  (2 * STAGE_BYTES)   // 112 KB

__device__ __forceinline__ uint32_t sw_off(int row, int c16) {
    return (uint32_t)(row * 128 + (((c16) ^ (row & 7)) << 4));
}

__global__ __launch_bounds__(256, 1)
void fgn_mma_kernel(const float* __restrict__ bias, float* __restrict__ out) {
    extern __shared__ char smem[];
    const uint32_t sb = smem_u32(smem);
    const int tid  = threadIdx.x;
    const int lane = tid & 31;
    const int wid  = tid >> 5;
    const int wm   = wid >> 2;          // 0..1 : m offset 32*wm
    const int wn   = wid & 3;           // 0..3 : n offset 16*wn
    const int m0   = blockIdx.y * TM;
    const int n0   = blockIdx.x * TN;

    // per-thread staging slots: u = tid + 256*j -> row = u>>3, c16 = u&7
    const int srow = tid >> 3;          // j=0 rows 0..31 ; j=1 rows 32..63
    const int sc   = tid & 7;

    auto load_chunk = [&](int stage, int ch) {
        const uint32_t base = sb + stage * STAGE_BYTES;
        const int k0 = ch * KC;
        const bf16* Aarr[3] = {g_xhi, g_xlo, g_x2};
        const int   Aoff[3] = {T_XHI, T_XLO, T_X2};
        #pragma unroll
        for (int a = 0; a < 3; a++)
            #pragma unroll
            for (int j = 0; j < 2; j++) {
                int row = srow + 32 * j;
                cpa16(base + Aoff[a] + sw_off(row, sc),
                      Aarr[a] + (size_t)(m0 + row) * I_DIM + k0 + sc * 8);
            }
        const bf16* Barr[4] = {g_whi, g_wlo, g_s2, g_nc2};
        const int   Boff[4] = {T_WHI, T_WLO, T_S2, T_NC2};
        #pragma unroll
        for (int b = 0; b < 4; b++)
            #pragma unroll
            for (int j = 0; j < 2; j++) {
                int row = srow + 32 * j;
                cpa16(base + Boff[b] + sw_off(row, sc),
                      Barr[b] + (size_t)(n0 + row) * I_DIM + k0 + sc * 8);
            }
    };

    float accL[2][2][4] = {};           // [m-tile][n-tile][c-frag]
    float accG[2][2][4] = {};

    const int lr = lane & 15;           // ldmatrix row-within-16
    const int lc = lane >> 4;           // ldmatrix k16-half select

    auto compute = [&](int stage) {
        const uint32_t base = sb + stage * STAGE_BYTES;
        #pragma unroll
        for (int ks = 0; ks < KC / 16; ks++) {
            const int c16 = 2 * ks + lc;
            uint32_t axh[2][4], axl[2][4], ax2[2][4];
            #pragma unroll
            for (int mt = 0; mt < 2; mt++) {
                int row = wm * 32 + mt * 16 + lr;
                uint32_t ad = base + sw_off(row, c16);
                LDMX4(axh[mt], ad + T_XHI);
                LDMX4(axl[mt], ad + T_XLO);
                LDMX4(ax2[mt], ad + T_X2);
            }
            int rowb = wn * 16 + lr;
            uint32_t bd = base + sw_off(rowb, c16);
            uint32_t bwh[4], bwl[4], bs2[4], bnc[4];
            LDMX4(bwh, bd + T_WHI);
            LDMX4(bwl, bd + T_WLO);
            LDMX4(bs2, bd + T_S2);
            LDMX4(bnc, bd + T_NC2);

            #pragma unroll
            for (int mt = 0; mt < 2; mt++)
                #pragma unroll
                for (int nt = 0; nt < 2; nt++) {
                    mma16816(accL[mt][nt], axh[mt], bwh[nt], bwh[nt + 2]); // hi*hi
                    mma16816(accL[mt][nt], axh[mt], bwl[nt], bwl[nt + 2]); // hi*lo
                    mma16816(accL[mt][nt], axl[mt], bwh[nt], bwh[nt + 2]); // lo*hi
                    mma16816(accG[mt][nt], ax2[mt], bs2[nt], bs2[nt + 2]); // x2*s2
                    mma16816(accG[mt][nt], axh[mt], bnc[nt], bnc[nt + 2]); // x*nc2
                }
        }
    };

    // -------- pipeline: 2-stage cp.async double buffer --------
    load_chunk(0, 0);
    CP_COMMIT();
    #pragma unroll 1
    for (int i = 0; i < NCH; i++) {
        if (i + 1 < NCH) {
            load_chunk((i + 1) & 1, i + 1);
            CP_COMMIT();
            CP_WAIT(1);
        } else {
            CP_WAIT(0);
        }
        __syncthreads();
        compute(i & 1);
        __syncthreads();
    }

    // -------- epilogue: out = (L + bias) * exp(-(G + K)) --------
    const int gq = lane >> 2;           // row-in-group
    const int tg = lane & 3;            // col pair
    #pragma unroll
    for (int mt = 0; mt < 2; mt++)
        #pragma unroll
        for (int nt = 0; nt < 2; nt++) {
            const float* L = accL[mt][nt];
            const float* G = accG[mt][nt];
            int gn = n0 + wn * 16 + nt * 8 + 2 * tg;
            float b0 = bias[gn],  b1 = bias[gn + 1];
            float k0 = g_K[gn],   k1 = g_K[gn + 1];
            int mlo = m0 + wm * 32 + mt * 16 + gq;
            float2 o0 = make_float2((L[0] + b0) * expf(-(G[0] + k0)),
                                    (L[1] + b1) * expf(-(G[1] + k1)));
            *(float2*)&out[(size_t)mlo * O_DIM + gn] = o0;
            float2 o1 = make_float2((L[2] + b0) * expf(-(G[2] + k0)),
                                    (L[3] + b1) * expf(-(G[3] + k1)));
            *(float2*)&out[(size_t)(mlo + 8) * O_DIM + gn] = o1;
        }
}

// ---------------- launch ----------------
extern "C" void kernel_launch(void* const* d_in, const int* in_sizes, int n_in,
                              void* d_out, int out_size)
{
    const float* X    = (const float*)d_in[0];
    const float* W    = (const float*)d_in[1];
    const float* bias = (const float*)d_in[2];
    const float* C    = (const float*)d_in[3];
    const float* V    = (const float*)d_in[4];
    (void)in_sizes; (void)n_in; (void)out_size;

    cudaFuncSetAttribute(fgn_mma_kernel,
                         cudaFuncAttributeMaxDynamicSharedMemorySize, SMEM_TOTAL);

    prep_x_kernel <<<B_DIM * I_DIM / 4 / 256, 256>>>(X);
    prep_w_kernel <<<O_DIM * I_DIM / 4 / 256, 256>>>(W);
    prep_cv_kernel<<<O_DIM, 128>>>(C, V);

    dim3 grid(O_DIM / TN, B_DIM / TM);   // 8 x 16 = 128 CTAs
    fgn_mma_kernel<<<grid, 256, SMEM_TOTAL>>>(bias, (float*)d_out);
}